// round 5
// baseline (speedup 1.0000x reference)
#include <cuda_runtime.h>

// Problem constants
#define VDIM 5000
#define MDIM 256
#define KDIM 64
#define NCH 40      // split-K chunks over V
#define CHUNK 128   // V elements per chunk (40*128 = 5120 >= 5000, padded)
#define LMB 0.001f
#define NITER 4

// ---------------------------------------------------------------------------
// Device scratch (allocation-free rule: __device__ globals)
// ---------------------------------------------------------------------------
__device__ float g_part[2 * NCH * 4 * 64 * 64];   // split-K partials (5.24 MB)
__device__ float g_A[64 * 256];                   // A  = tx @ fx
__device__ float g_T[64 * 256];                   // T  = ty @ fy
__device__ float g_AAt[4096];                     // A A^T
__device__ float g_TA[4096];                      // T A^T
__device__ float g_S[4096];                       // sy^T sy
__device__ float g_Qm[4096];                      // inv(sx)
__device__ float g_Sinv[4096];                    // inv(S)
__device__ float g_AAti[4096];                    // inv(AAt)
__device__ float g_Rp[4096];                      // R' = S * TA  (rhs matrix)
__device__ float g_QtP[4096];                     // Q^T diag(ex) Q  (symmetric)
__device__ float g_QtQ[4096];                     // Q^T Q
__device__ float g_U1[4096];                      // AAt + LMB * P^T P
__device__ float g_L3[4096];                      // LMB * Sinv * diag(ey) * S
__device__ float g_L4[4096];                      // L3 * diag(ey)
__device__ float g_R1[4096];                      // U1  * AAti
__device__ float g_R2[4096];                      // QtP * AAti
__device__ float g_R4[4096];                      // QtQ * AAti
__device__ float g_Tmp[4096];                     // Sinv * R'
__device__ float g_X0[4096];                      // Sinv * R' * AAti (precond rhs)
__device__ float g_X[4096];                       // iterate / solution
__device__ float g_M1[4096], g_M2[4096], g_M4[4096];

// ---------------------------------------------------------------------------
// 1) Big GEMMs: A = tx[64,V] @ fx[V,256], T = ty @ fy.  Split-K, deterministic.
//    grid = (NCH, 4 col-tiles of 64, 2 matrices), block = 256
// ---------------------------------------------------------------------------
__global__ void big_gemm(const float* __restrict__ fx, const float* __restrict__ fy,
                         const float* __restrict__ tx, const float* __restrict__ ty) {
    int ch = blockIdx.x, ct = blockIdx.y, mz = blockIdx.z;
    const float* f = mz ? fy : fx;   // [V][256]
    const float* t = mz ? ty : tx;   // [64][V]

    __shared__ float ts[64][17];
    __shared__ float fs[16][64];

    int tid = threadIdx.x;
    int row = tid & 63;
    int cg  = tid >> 6;              // 4 column groups of 16

    float acc[16];
#pragma unroll
    for (int i = 0; i < 16; i++) acc[i] = 0.f;

    int k0 = ch * CHUNK;
    for (int sub = 0; sub < CHUNK / 16; ++sub) {
        int kb = k0 + sub * 16;
        // load t tile: 64 rows x 16 k
#pragma unroll
        for (int i = 0; i < 4; i++) {
            int idx = tid + i * 256;
            int r = idx >> 4, kk = idx & 15;
            int k = kb + kk;
            ts[r][kk] = (k < VDIM) ? t[r * VDIM + k] : 0.f;
        }
        // load f tile: 16 k x 64 cols
#pragma unroll
        for (int i = 0; i < 4; i++) {
            int idx = tid + i * 256;
            int kk = idx >> 6, c = idx & 63;
            int k = kb + kk;
            fs[kk][c] = (k < VDIM) ? f[k * MDIM + ct * 64 + c] : 0.f;
        }
        __syncthreads();
#pragma unroll
        for (int kk = 0; kk < 16; kk++) {
            float a = ts[row][kk];
#pragma unroll
            for (int c = 0; c < 16; c++) acc[c] += a * fs[kk][cg * 16 + c];
        }
        __syncthreads();
    }
    float* p = &g_part[((((size_t)mz * NCH + ch) * 4 + ct) * 64 + row) * 64 + cg * 16];
#pragma unroll
    for (int c = 0; c < 16; c++) p[c] = acc[c];
}

// Deterministic fixed-order reduction of split-K partials -> g_A, g_T.
// Extra blocks (128..131) also compute S = sy^T sy (independent of A/T).
__global__ void reduce_AT(const float* __restrict__ sy) {
    if (blockIdx.x >= 128) {
        int slab = blockIdx.x - 128, tid = threadIdx.x;
        for (int i = 0; i < 4; i++) {
            int o = tid + i * 256;
            int r = slab * 16 + (o >> 6), c = o & 63;
            float s = 0.f;
            for (int k = 0; k < 64; k++) s += sy[k * 64 + r] * sy[k * 64 + c];
            g_S[r * 64 + c] = s;
        }
        return;
    }
    int idx = blockIdx.x * 256 + threadIdx.x;  // 0..32767
    int mz  = idx >> 14;
    int rem = idx & 16383;
    int r   = rem >> 8;
    int c   = rem & 255;
    int ct  = c >> 6, cc = c & 63;
    float s = 0.f;
    for (int ch = 0; ch < NCH; ch++)
        s += g_part[((((size_t)mz * NCH + ch) * 4 + ct) * 64 + r) * 64 + cc];
    (mz ? g_T : g_A)[r * 256 + c] = s;
}

// ---------------------------------------------------------------------------
// 2) setup1: AAt = A A^T, TA = T A^T (K=256).  grid = 8 (2 jobs x 4 slabs)
// ---------------------------------------------------------------------------
__global__ void setup1() {
    int job = blockIdx.x >> 2, slab = blockIdx.x & 3;
    int tid = threadIdx.x;
    const float* L = job ? g_T : g_A;
    float* C = job ? g_TA : g_AAt;
    for (int i = 0; i < 4; i++) {
        int o = tid + i * 256;
        int r = slab * 16 + (o >> 6), c = o & 63;
        float s = 0.f;
        for (int k = 0; k < 256; k++) s += L[r * 256 + k] * g_A[c * 256 + k];
        C[r * 64 + c] = s;
    }
}

// ---------------------------------------------------------------------------
// Gauss-Jordan 64x64 inversion, no pivoting (inputs SPD or ~I), 1 block of 256.
// Augmented matrix is 64 x 128; each thread owns row (tid&63) and one of 4
// column groups of 32 (flat over the 128 columns).
// ---------------------------------------------------------------------------
__device__ void gj_inv(const float* __restrict__ Ain, float* __restrict__ Aout) {
    __shared__ float aug[64][129];   // 128 cols + pad
    __shared__ float pinv;
    int tid = threadIdx.x;
    int r = tid & 63, j0 = (tid >> 6) * 32;
    for (int jj = 0; jj < 32; jj++) {
        int j = j0 + jj;
        aug[r][j] = (j < 64) ? Ain[r * 64 + j] : ((r == (j - 64)) ? 1.f : 0.f);
    }
    __syncthreads();
    for (int p = 0; p < 64; p++) {
        if (tid == 0) pinv = 1.f / aug[p][p];
        __syncthreads();
        if (r == p)
            for (int jj = 0; jj < 32; jj++) aug[p][j0 + jj] *= pinv;
        __syncthreads();
        float f = aug[r][p];          // read before elimination writes
        __syncthreads();
        if (r != p)
            for (int jj = 0; jj < 32; jj++) aug[r][j0 + jj] -= f * aug[p][j0 + jj];
        __syncthreads();
    }
    for (int jj = 0; jj < 32; jj++) {
        int j = j0 + jj;
        if (j >= 64) Aout[r * 64 + (j - 64)] = aug[r][j];
    }
}

// setup2: block0 inv(sx), block1 inv(S), block2 inv(AAt), blocks3-6: R' = S*TA
__global__ void setup2(const float* __restrict__ sx) {
    int b = blockIdx.x;
    if (b == 0)      gj_inv(sx,    g_Qm);
    else if (b == 1) gj_inv(g_S,   g_Sinv);
    else if (b == 2) gj_inv(g_AAt, g_AAti);
    else {
        int slab = b - 3, tid = threadIdx.x;
        for (int i = 0; i < 4; i++) {
            int o = tid + i * 256;
            int r = slab * 16 + (o >> 6), c = o & 63;
            float s = 0.f;
            for (int k = 0; k < 64; k++) s += g_S[r * 64 + k] * g_TA[k * 64 + c];
            g_Rp[r * 64 + c] = s;
        }
    }
}

// setup3: QtP, QtQ, U1 = AAt + LMB*PtP, L3 = LMB*Sinv*diag(ey)*S.  grid=16
__global__ void setup3(const float* __restrict__ ex, const float* __restrict__ ey) {
    int job = blockIdx.x >> 2, slab = blockIdx.x & 3, tid = threadIdx.x;
    for (int i = 0; i < 4; i++) {
        int o = tid + i * 256;
        int r = slab * 16 + (o >> 6), c = o & 63;
        float s = 0.f;
        if (job == 0) {
            for (int k = 0; k < 64; k++) s += g_Qm[k * 64 + r] * ex[k] * g_Qm[k * 64 + c];
            g_QtP[r * 64 + c] = s;
        } else if (job == 1) {
            for (int k = 0; k < 64; k++) s += g_Qm[k * 64 + r] * g_Qm[k * 64 + c];
            g_QtQ[r * 64 + c] = s;
        } else if (job == 2) {
            for (int k = 0; k < 64; k++) { float e = ex[k]; s += e * e * g_Qm[k * 64 + r] * g_Qm[k * 64 + c]; }
            g_U1[r * 64 + c] = g_AAt[r * 64 + c] + LMB * s;
        } else {
            for (int k = 0; k < 64; k++) s += g_Sinv[r * 64 + k] * ey[k] * g_S[k * 64 + c];
            g_L3[r * 64 + c] = LMB * s;
        }
    }
}

// setup4: R1=U1*AAti, R2=QtP*AAti, R4=QtQ*AAti, Tmp=Sinv*R', L4=L3*diag(ey). grid=20
__global__ void setup4(const float* __restrict__ ey) {
    int job = blockIdx.x >> 2, slab = blockIdx.x & 3, tid = threadIdx.x;
    for (int i = 0; i < 4; i++) {
        int o = tid + i * 256;
        int r = slab * 16 + (o >> 6), c = o & 63;
        if (job == 4) { g_L4[r * 64 + c] = g_L3[r * 64 + c] * ey[c]; continue; }
        const float* Am; float* Cm;
        const float* Bm = (job == 3) ? g_Rp : g_AAti;
        if (job == 0)      { Am = g_U1;   Cm = g_R1; }
        else if (job == 1) { Am = g_QtP;  Cm = g_R2; }
        else if (job == 2) { Am = g_QtQ;  Cm = g_R4; }
        else               { Am = g_Sinv; Cm = g_Tmp; }
        float s = 0.f;
        for (int k = 0; k < 64; k++) s += Am[r * 64 + k] * Bm[k * 64 + c];
        Cm[r * 64 + c] = s;
    }
}

// setup5: X0 = Tmp * AAti; X = X0.  grid=4
__global__ void setup5() {
    int slab = blockIdx.x, tid = threadIdx.x;
    for (int i = 0; i < 4; i++) {
        int o = tid + i * 256;
        int r = slab * 16 + (o >> 6), c = o & 63;
        float s = 0.f;
        for (int k = 0; k < 64; k++) s += g_Tmp[r * 64 + k] * g_AAti[k * 64 + c];
        g_X0[r * 64 + c] = s;
        g_X[r * 64 + c]  = s;
    }
}

// ---------------------------------------------------------------------------
// Richardson iteration (preconditioned):
//   X <- X + X0 - X*R1 + LMB*diag(ey)*(X*R2) + L3*(X*R2) - L4*(X*R4)
// ---------------------------------------------------------------------------
__global__ void iterA() {   // M1 = X*R1, M2 = X*R2, M4 = X*R4.  grid=12
    int job = blockIdx.x >> 2, slab = blockIdx.x & 3, tid = threadIdx.x;
    const float* Bm = (job == 0) ? g_R1 : (job == 1) ? g_R2 : g_R4;
    float* Cm       = (job == 0) ? g_M1 : (job == 1) ? g_M2 : g_M4;
    for (int i = 0; i < 4; i++) {
        int o = tid + i * 256;
        int r = slab * 16 + (o >> 6), c = o & 63;
        float s = 0.f;
        for (int k = 0; k < 64; k++) s += g_X[r * 64 + k] * Bm[k * 64 + c];
        Cm[r * 64 + c] = s;
    }
}

// combine; on the final iteration also writes the output buffer. grid=4
__global__ void iterB(const float* __restrict__ ey, float* __restrict__ out) {
    int slab = blockIdx.x, tid = threadIdx.x;
    for (int i = 0; i < 4; i++) {
        int o = tid + i * 256;
        int r = slab * 16 + (o >> 6), c = o & 63;
        float s = g_X[r * 64 + c] + g_X0[r * 64 + c] - g_M1[r * 64 + c]
                + LMB * ey[r] * g_M2[r * 64 + c];
        for (int k = 0; k < 64; k++)
            s += g_L3[r * 64 + k] * g_M2[k * 64 + c] - g_L4[r * 64 + k] * g_M4[k * 64 + c];
        g_X[r * 64 + c] = s;
        if (out) out[r * 64 + c] = s;
    }
}

// ---------------------------------------------------------------------------
// Launch: graph-capturable, allocation-free, deterministic.
// ---------------------------------------------------------------------------
extern "C" void kernel_launch(void* const* d_in, const int* in_sizes, int n_in,
                              void* d_out, int out_size) {
    // Map inputs by element count; pairs keep x-then-y order.
    const float *fx = nullptr, *fy = nullptr, *ex = nullptr, *ey = nullptr;
    const float *tx = nullptr, *ty = nullptr, *sx = nullptr, *sy = nullptr;
    int nFeat = 0, nEval = 0, nEvec = 0, nSq = 0;
    for (int i = 0; i < n_in; i++) {
        const float* p = (const float*)d_in[i];
        int n = in_sizes[i];
        if (n == VDIM * MDIM)      { if (nFeat++ == 0) fx = p; else fy = p; }
        else if (n == KDIM)        { if (nEval++ == 0) ex = p; else ey = p; }
        else if (n == KDIM * VDIM) { if (nEvec++ == 0) tx = p; else ty = p; }
        else if (n == KDIM * KDIM) { if (nSq++   == 0) sx = p; else sy = p; }
    }

    dim3 gB(NCH, 4, 2);
    big_gemm<<<gB, 256>>>(fx, fy, tx, ty);
    reduce_AT<<<132, 256>>>(sy);
    setup1<<<8, 256>>>();
    setup2<<<7, 256>>>(sx);
    setup3<<<16, 256>>>(ex, ey);
    setup4<<<20, 256>>>(ey);
    setup5<<<4, 256>>>();
    for (int it = 0; it < NITER; ++it) {
        iterA<<<12, 256>>>();
        iterB<<<4, 256>>>(ey, (it == NITER - 1) ? (float*)d_out : nullptr);
    }
}

// round 6
// speedup vs baseline: 2.5730x; 2.5730x over previous
#include <cuda_runtime.h>

#define VDIM 5000
#define MDIM 256
#define NCH 35        // split-K chunks: 35*144 = 5040 >= 5000
#define CHUNK 144
#define LMB 0.001f
#define NITER 4

// ---------------------------------------------------------------------------
// Device scratch (allocation-free rule), 16B-aligned for float4 access
// ---------------------------------------------------------------------------
__device__ __align__(16) float g_part[2 * NCH * 4 * 64 * 64];
__device__ __align__(16) float g_A[64 * 256], g_T[64 * 256];
__device__ __align__(16) float g_S[4096];
__device__ __align__(16) float g_AAt[4096], g_TA[4096];
__device__ __align__(16) float g_Qm[4096], g_Sinv[4096], g_AAti[4096];
__device__ __align__(16) float g_QtP[4096], g_QtQ[4096], g_U1[4096];
__device__ __align__(16) float g_L3[4096], g_L4[4096];
__device__ __align__(16) float g_R1[4096], g_R2[4096], g_R4[4096];
__device__ __align__(16) float g_X0[4096], g_X[4096];
__device__ __align__(16) float g_M1[4096], g_M2[4096], g_M4[4096];

// ---------------------------------------------------------------------------
// Big GEMMs: A = tx[64,V] @ fx[V,256], T = ty @ fy.  4x4 microtile, split-K.
// grid = (NCH, 4 col-tiles, 2), block = 256
// ---------------------------------------------------------------------------
__global__ void big_gemm(const float* __restrict__ fx, const float* __restrict__ fy,
                         const float* __restrict__ tx, const float* __restrict__ ty) {
    int ch = blockIdx.x, ct = blockIdx.y, mz = blockIdx.z;
    const float* f = mz ? fy : fx;   // [V][256]
    const float* t = mz ? ty : tx;   // [64][V]

    __shared__ __align__(16) float tsT[16][68];   // [kk][row], padded (68*4=272B, 16B-mult)
    __shared__ __align__(16) float fs[16][64];    // [kk][col]

    int tid = threadIdx.x;
    int r0 = (tid >> 4) * 4;
    int c0 = (tid & 15) * 4;

    float acc[4][4];
#pragma unroll
    for (int i = 0; i < 4; i++)
#pragma unroll
        for (int j = 0; j < 4; j++) acc[i][j] = 0.f;

    int lr = tid >> 2, lkq = (tid & 3) * 4;    // t-tile loader
    int fkk = tid >> 4, fcb = (tid & 15) * 4;  // f-tile loader

    int k0 = ch * CHUNK;
    for (int sub = 0; sub < CHUNK / 16; ++sub) {
        int kb = k0 + sub * 16;
#pragma unroll
        for (int q = 0; q < 4; q++) {
            int k = kb + lkq + q;
            tsT[lkq + q][lr] = (k < VDIM) ? t[lr * VDIM + k] : 0.f;
        }
        {
            int k = kb + fkk;
            float4 fv = make_float4(0.f, 0.f, 0.f, 0.f);
            if (k < VDIM) fv = *(const float4*)&f[k * MDIM + ct * 64 + fcb];
            *(float4*)&fs[fkk][fcb] = fv;
        }
        __syncthreads();
#pragma unroll
        for (int kk = 0; kk < 16; kk++) {
            float4 av = *(const float4*)&tsT[kk][r0];
            float4 bv = *(const float4*)&fs[kk][c0];
            float a[4] = {av.x, av.y, av.z, av.w};
            float b[4] = {bv.x, bv.y, bv.z, bv.w};
#pragma unroll
            for (int i = 0; i < 4; i++)
#pragma unroll
                for (int j = 0; j < 4; j++) acc[i][j] += a[i] * b[j];
        }
        __syncthreads();
    }
    size_t base = (((size_t)mz * NCH + ch) * 4 + ct) * 4096;
#pragma unroll
    for (int i = 0; i < 4; i++)
        *(float4*)&g_part[base + (size_t)(r0 + i) * 64 + c0] =
            make_float4(acc[i][0], acc[i][1], acc[i][2], acc[i][3]);
}

// Deterministic reduction of split-K partials -> g_A, g_T; blocks 128+ do S.
__global__ void reduce_AT(const float* __restrict__ sy) {
    if (blockIdx.x >= 128) {
        int slab = blockIdx.x - 128, tid = threadIdx.x;
        for (int i = 0; i < 4; i++) {
            int o = tid + i * 256;
            int r = slab * 16 + (o >> 6), c = o & 63;
            float s = 0.f;
            for (int k = 0; k < 64; k++) s += sy[k * 64 + r] * sy[k * 64 + c];
            g_S[r * 64 + c] = s;
        }
        return;
    }
    int idx = blockIdx.x * 256 + threadIdx.x;
    int mz = idx >> 14, rem = idx & 16383;
    int r = rem >> 8, c = rem & 255;
    int ct = c >> 6, cc = c & 63;
    float s = 0.f;
    for (int ch = 0; ch < NCH; ch++)
        s += g_part[(((size_t)mz * NCH + ch) * 4 + ct) * 4096 + r * 64 + cc];
    (mz ? g_T : g_A)[r * 256 + c] = s;
}

// ---------------------------------------------------------------------------
// Cluster phase barrier: gpu-scope release fence (CCTL.IVALL) + cluster barrier
// ---------------------------------------------------------------------------
__device__ __forceinline__ void csync() {
    __threadfence();
    asm volatile("barrier.cluster.arrive.aligned;" ::: "memory");
    asm volatile("barrier.cluster.wait.aligned;" ::: "memory");
}

// ---------------------------------------------------------------------------
// Register-resident Gauss-Jordan 64x64 inversion (no pivoting; SPD / ~I).
// 256 threads: thread (r = tid&63, cg = tid>>6) owns 32 cols of the 64x128
// augmented matrix in registers. Pivot row + pivot column double-buffered in
// shared -> 1 barrier per pivot. Deferred normalization.
// ---------------------------------------------------------------------------
__device__ __noinline__ void gj_inv(const float* __restrict__ Ain, float* __restrict__ Aout) {
    __shared__ float pr[2][128];
    __shared__ float fc[2][64];
    int tid = threadIdx.x;
    int r = tid & 63, cg = tid >> 6, j0 = cg * 32;
    float a[32];
#pragma unroll
    for (int jj = 0; jj < 32; jj++) {
        int j = j0 + jj;
        a[jj] = (j < 64) ? Ain[r * 64 + j] : ((j - 64 == r) ? 1.f : 0.f);
    }
    if (cg == 0) fc[0][r] = a[0];
    if (r == 0) {
#pragma unroll
        for (int jj = 0; jj < 32; jj++) pr[0][j0 + jj] = a[jj];
    }
    __syncthreads();
    float mydiag = 1.f;
    for (int p = 0; p < 64; p++) {
        int cur = p & 1, nxt = cur ^ 1;
        float apiv = fc[cur][p];
        float scale = fc[cur][r] / apiv;
        if (r == p) mydiag = apiv;
        if (r != p) {
#pragma unroll
            for (int jj = 0; jj < 32; jj++) a[jj] -= scale * pr[cur][j0 + jj];
        }
        if (p < 63) {
            int q = p + 1;
#pragma unroll
            for (int jj = 0; jj < 32; jj++)
                if (j0 + jj == q) fc[nxt][r] = a[jj];
            if (r == q) {
#pragma unroll
                for (int jj = 0; jj < 32; jj++) pr[nxt][j0 + jj] = a[jj];
            }
        }
        __syncthreads();
    }
    if (cg >= 2) {
        float dinv = 1.f / mydiag;
#pragma unroll
        for (int jj = 0; jj < 32; jj++)
            Aout[r * 64 + (j0 - 64) + jj] = a[jj] * dinv;
    }
}

// ---------------------------------------------------------------------------
// Small-GEMM helpers: one 16-row slab of a 64x64 output, 256 threads
// ---------------------------------------------------------------------------
// C[r][c] = sum_k L[r*256+k] * R[c*256+k]  (K=256, NT)
__device__ void dot_nt256(const float* __restrict__ L, const float* __restrict__ R,
                          float* __restrict__ C, int slab) {
    int tid = threadIdx.x;
    int r = slab * 16 + (tid >> 4), c0 = (tid & 15) * 4;
    float s0 = 0.f, s1 = 0.f, s2 = 0.f, s3 = 0.f;
    for (int k4 = 0; k4 < 64; k4++) {
        float4 lv = *(const float4*)&L[r * 256 + k4 * 4];
        float4 a0 = *(const float4*)&R[(c0 + 0) * 256 + k4 * 4];
        float4 a1 = *(const float4*)&R[(c0 + 1) * 256 + k4 * 4];
        float4 a2 = *(const float4*)&R[(c0 + 2) * 256 + k4 * 4];
        float4 a3 = *(const float4*)&R[(c0 + 3) * 256 + k4 * 4];
        s0 += lv.x * a0.x + lv.y * a0.y + lv.z * a0.z + lv.w * a0.w;
        s1 += lv.x * a1.x + lv.y * a1.y + lv.z * a1.z + lv.w * a1.w;
        s2 += lv.x * a2.x + lv.y * a2.y + lv.z * a2.z + lv.w * a2.w;
        s3 += lv.x * a3.x + lv.y * a3.y + lv.z * a3.z + lv.w * a3.w;
    }
    *(float4*)&C[r * 64 + c0] = make_float4(s0, s1, s2, s3);
}

// C = A(64x64) * B(64x64), one slab; optional duplicate destination C2
__device__ void dot64(const float* __restrict__ A, const float* __restrict__ B,
                      float* __restrict__ C, int slab, float* __restrict__ C2) {
    int tid = threadIdx.x;
    int r = slab * 16 + (tid >> 4), c0 = (tid & 15) * 4;
    float4 acc = make_float4(0.f, 0.f, 0.f, 0.f);
    for (int k = 0; k < 64; k++) {
        float av = A[r * 64 + k];
        float4 bv = *(const float4*)&B[k * 64 + c0];
        acc.x += av * bv.x; acc.y += av * bv.y;
        acc.z += av * bv.z; acc.w += av * bv.w;
    }
    *(float4*)&C[r * 64 + c0] = acc;
    if (C2) *(float4*)&C2[r * 64 + c0] = acc;
}

// C = scale * A * diag(w) * B, one slab
__device__ void dot64w(const float* __restrict__ A, const float* __restrict__ B,
                       const float* __restrict__ w, float scale,
                       float* __restrict__ C, int slab) {
    int tid = threadIdx.x;
    int r = slab * 16 + (tid >> 4), c0 = (tid & 15) * 4;
    float4 acc = make_float4(0.f, 0.f, 0.f, 0.f);
    for (int k = 0; k < 64; k++) {
        float av = A[r * 64 + k] * w[k];
        float4 bv = *(const float4*)&B[k * 64 + c0];
        acc.x += av * bv.x; acc.y += av * bv.y;
        acc.z += av * bv.z; acc.w += av * bv.w;
    }
    *(float4*)&C[r * 64 + c0] = make_float4(acc.x * scale, acc.y * scale,
                                            acc.z * scale, acc.w * scale);
}

// Fused: QtP = Qm^T diag(ex) Qm, QtQ = Qm^T Qm, U1 = AAt + LMB*Qm^T diag(ex^2) Qm
__device__ void qt_fused(const float* __restrict__ ex, int slab) {
    int tid = threadIdx.x;
    int r = slab * 16 + (tid >> 4), c0 = (tid & 15) * 4;
    float4 ap = make_float4(0, 0, 0, 0), aq = ap, au = ap;
    for (int k = 0; k < 64; k++) {
        float qr = g_Qm[k * 64 + r];
        float e = ex[k];
        float4 qc = *(const float4*)&g_Qm[k * 64 + c0];
        float t = qr * e, t2 = t * e;
        ap.x += t * qc.x;  ap.y += t * qc.y;  ap.z += t * qc.z;  ap.w += t * qc.w;
        aq.x += qr * qc.x; aq.y += qr * qc.y; aq.z += qr * qc.z; aq.w += qr * qc.w;
        au.x += t2 * qc.x; au.y += t2 * qc.y; au.z += t2 * qc.z; au.w += t2 * qc.w;
    }
    *(float4*)&g_QtP[r * 64 + c0] = ap;
    *(float4*)&g_QtQ[r * 64 + c0] = aq;
    float4 av = *(const float4*)&g_AAt[r * 64 + c0];
    *(float4*)&g_U1[r * 64 + c0] = make_float4(av.x + LMB * au.x, av.y + LMB * au.y,
                                               av.z + LMB * au.z, av.w + LMB * au.w);
}

// X <- X + X0 - M1 + LMB*diag(ey)*M2 + L3*M2 - L4*M4  (one slab)
__device__ void iterB_slab(int slab, const float* __restrict__ ey, float* __restrict__ out) {
    int tid = threadIdx.x;
    int r = slab * 16 + (tid >> 4), c0 = (tid & 15) * 4;
    float eyr = LMB * ey[r];
    float4 xv = *(const float4*)&g_X[r * 64 + c0];
    float4 x0 = *(const float4*)&g_X0[r * 64 + c0];
    float4 m1 = *(const float4*)&g_M1[r * 64 + c0];
    float4 m2 = *(const float4*)&g_M2[r * 64 + c0];
    float4 s = make_float4(xv.x + x0.x - m1.x + eyr * m2.x,
                           xv.y + x0.y - m1.y + eyr * m2.y,
                           xv.z + x0.z - m1.z + eyr * m2.z,
                           xv.w + x0.w - m1.w + eyr * m2.w);
    for (int k = 0; k < 64; k++) {
        float l3 = g_L3[r * 64 + k], l4 = g_L4[r * 64 + k];
        float4 a = *(const float4*)&g_M2[k * 64 + c0];
        float4 b = *(const float4*)&g_M4[k * 64 + c0];
        s.x += l3 * a.x - l4 * b.x;  s.y += l3 * a.y - l4 * b.y;
        s.z += l3 * a.z - l4 * b.z;  s.w += l3 * a.w - l4 * b.w;
    }
    *(float4*)&g_X[r * 64 + c0] = s;
    if (out) *(float4*)&out[r * 64 + c0] = s;
}

// ---------------------------------------------------------------------------
// Mega kernel: all post-reduce work, one 8-CTA cluster, phase-synchronized.
// ---------------------------------------------------------------------------
__global__ void __cluster_dims__(8, 1, 1) __launch_bounds__(256, 1)
mega(const float* __restrict__ sx, const float* __restrict__ ex,
     const float* __restrict__ ey, float* __restrict__ out) {
    int b = blockIdx.x;

    // P1: inversions of sx and S; AAt; first half of TA
    if (b == 0)      gj_inv(sx, g_Qm);
    else if (b == 1) gj_inv(g_S, g_Sinv);
    else if (b < 6)  dot_nt256(g_A, g_A, g_AAt, b - 2);
    else             dot_nt256(g_T, g_A, g_TA, b - 6);
    csync();

    // P2: inv(AAt); rest of TA; fused QtP/QtQ/U1; L3
    if (b == 0)      gj_inv(g_AAt, g_AAti);
    else if (b < 3)  dot_nt256(g_T, g_A, g_TA, b + 1);
    else if (b < 7)  qt_fused(ex, b - 3);
    else
        for (int s = 0; s < 4; s++) dot64w(g_Sinv, g_S, ey, LMB, g_L3, s);
    csync();

    // P3: R1, R2, R4, X0 (=TA*AAti, copied to X), L4   (17 units)
    for (int u = b; u < 17; u += 8) {
        if (u < 4)       dot64(g_U1, g_AAti, g_R1, u, 0);
        else if (u < 8)  dot64(g_QtP, g_AAti, g_R2, u - 4, 0);
        else if (u < 12) dot64(g_QtQ, g_AAti, g_R4, u - 8, 0);
        else if (u < 16) dot64(g_TA, g_AAti, g_X0, u - 12, g_X);
        else {
            int tid = threadIdx.x;
            for (int i = 0; i < 16; i++) {
                int o = tid * 16 + i;
                g_L4[o] = g_L3[o] * ey[o & 63];
            }
        }
    }
    csync();

    // Richardson iterations
    for (int it = 0; it < NITER; it++) {
        for (int u = b; u < 12; u += 8) {
            if (u < 4)      dot64(g_X, g_R1, g_M1, u, 0);
            else if (u < 8) dot64(g_X, g_R2, g_M2, u - 4, 0);
            else            dot64(g_X, g_R4, g_M4, u - 8, 0);
        }
        csync();
        if (b < 4) iterB_slab(b, ey, (it == NITER - 1) ? out : 0);
        csync();
    }
}

// ---------------------------------------------------------------------------
// Launch: graph-capturable, allocation-free, deterministic.  3 nodes.
// ---------------------------------------------------------------------------
extern "C" void kernel_launch(void* const* d_in, const int* in_sizes, int n_in,
                              void* d_out, int out_size) {
    const float *fx = 0, *fy = 0, *ex = 0, *ey = 0, *tx = 0, *ty = 0, *sx = 0, *sy = 0;
    int nFeat = 0, nEval = 0, nEvec = 0, nSq = 0;
    for (int i = 0; i < n_in; i++) {
        const float* p = (const float*)d_in[i];
        int n = in_sizes[i];
        if (n == VDIM * MDIM)    { if (nFeat++ == 0) fx = p; else fy = p; }
        else if (n == 64)        { if (nEval++ == 0) ex = p; else ey = p; }
        else if (n == 64 * VDIM) { if (nEvec++ == 0) tx = p; else ty = p; }
        else if (n == 64 * 64)   { if (nSq++   == 0) sx = p; else sy = p; }
    }

    dim3 gB(NCH, 4, 2);
    big_gemm<<<gB, 256>>>(fx, fy, tx, ty);
    reduce_AT<<<132, 256>>>(sy);
    mega<<<8, 256>>>(sx, ex, ey, (float*)d_out);
}

// round 7
// speedup vs baseline: 2.7601x; 1.0727x over previous
#include <cuda_runtime.h>

#define VDIM 5000
#define MDIM 256
#define NCH 63        // split-K chunks: 63*80 = 5040 >= 5000
#define CHUNK 80
#define LMB 0.001f
#define NITER 3

// ---------------------------------------------------------------------------
// Device scratch (allocation-free rule), 16B-aligned for float4 access
// ---------------------------------------------------------------------------
__device__ __align__(16) float g_part[2 * NCH * 4 * 64 * 64];
__device__ __align__(16) float g_A[64 * 256], g_T[64 * 256];
__device__ __align__(16) float g_S[4096];
__device__ __align__(16) float g_AAt[4096], g_TA[4096];
__device__ __align__(16) float g_Qm[4096], g_Sinv[4096], g_AAti[4096];
__device__ __align__(16) float g_QtP[4096], g_QtQ[4096], g_U1[4096];
__device__ __align__(16) float g_L3[4096], g_L4[4096];
__device__ __align__(16) float g_R1[4096], g_R2[4096], g_R4[4096];
__device__ __align__(16) float g_X0[4096], g_X[4096];
__device__ __align__(16) float g_M1[4096], g_M2[4096], g_M4[4096];

// ---------------------------------------------------------------------------
// Big GEMMs: A = tx[64,V] @ fx[V,256], T = ty @ fy.  4x4 microtile, split-K.
// grid = (NCH, 4 col-tiles, 2), block = 256
// ---------------------------------------------------------------------------
__global__ void __launch_bounds__(256) big_gemm(
        const float* __restrict__ fx, const float* __restrict__ fy,
        const float* __restrict__ tx, const float* __restrict__ ty) {
    int ch = blockIdx.x, ct = blockIdx.y, mz = blockIdx.z;
    const float* f = mz ? fy : fx;   // [V][256]
    const float* t = mz ? ty : tx;   // [64][V]

    __shared__ __align__(16) float tsT[16][68];   // [kk][row], padded
    __shared__ __align__(16) float fs[16][64];    // [kk][col]

    int tid = threadIdx.x;
    int r0 = (tid >> 4) * 4;
    int c0 = (tid & 15) * 4;

    float acc[4][4];
#pragma unroll
    for (int i = 0; i < 4; i++)
#pragma unroll
        for (int j = 0; j < 4; j++) acc[i][j] = 0.f;

    int lr = tid >> 2, lkq = (tid & 3) * 4;    // t-tile loader
    int fkk = tid >> 4, fcb = (tid & 15) * 4;  // f-tile loader

    int k0 = ch * CHUNK;
    for (int sub = 0; sub < CHUNK / 16; ++sub) {
        int kb = k0 + sub * 16;
#pragma unroll
        for (int q = 0; q < 4; q++) {
            int k = kb + lkq + q;
            tsT[lkq + q][lr] = (k < VDIM) ? t[lr * VDIM + k] : 0.f;
        }
        {
            int k = kb + fkk;
            float4 fv = make_float4(0.f, 0.f, 0.f, 0.f);
            if (k < VDIM) fv = *(const float4*)&f[k * MDIM + ct * 64 + fcb];
            *(float4*)&fs[fkk][fcb] = fv;
        }
        __syncthreads();
#pragma unroll
        for (int kk = 0; kk < 16; kk++) {
            float4 av = *(const float4*)&tsT[kk][r0];
            float4 bv = *(const float4*)&fs[kk][c0];
            float a[4] = {av.x, av.y, av.z, av.w};
            float b[4] = {bv.x, bv.y, bv.z, bv.w};
#pragma unroll
            for (int i = 0; i < 4; i++)
#pragma unroll
                for (int j = 0; j < 4; j++) acc[i][j] += a[i] * b[j];
        }
        __syncthreads();
    }
    size_t base = (((size_t)mz * NCH + ch) * 4 + ct) * 4096;
#pragma unroll
    for (int i = 0; i < 4; i++)
        *(float4*)&g_part[base + (size_t)(r0 + i) * 64 + c0] =
            make_float4(acc[i][0], acc[i][1], acc[i][2], acc[i][3]);
}

// Deterministic reduction of split-K partials -> g_A, g_T; blocks 128+ do S.
__global__ void reduce_AT(const float* __restrict__ sy) {
    if (blockIdx.x >= 128) {
        int slab = blockIdx.x - 128, tid = threadIdx.x;
        for (int i = 0; i < 4; i++) {
            int o = tid + i * 256;
            int r = slab * 16 + (o >> 6), c = o & 63;
            float s = 0.f;
            for (int k = 0; k < 64; k++) s += sy[k * 64 + r] * sy[k * 64 + c];
            g_S[r * 64 + c] = s;
        }
        return;
    }
    int idx = blockIdx.x * 256 + threadIdx.x;
    int mz = idx >> 14, rem = idx & 16383;
    int r = rem >> 8, c = rem & 255;
    int ct = c >> 6, cc = c & 63;
    float s = 0.f;
    for (int ch = 0; ch < NCH; ch++)
        s += g_part[(((size_t)mz * NCH + ch) * 4 + ct) * 4096 + r * 64 + cc];
    (mz ? g_T : g_A)[r * 256 + c] = s;
}

// ---------------------------------------------------------------------------
// Cluster phase barrier. Cluster-scope fence (emits CCTL.IVALL, NO gpu-scope
// membar drain) + cluster barrier (release/acquire at cluster scope).
// ---------------------------------------------------------------------------
__device__ __forceinline__ void csync() {
    asm volatile("fence.acq_rel.cluster;" ::: "memory");
    asm volatile("barrier.cluster.arrive.aligned;" ::: "memory");
    asm volatile("barrier.cluster.wait.aligned;" ::: "memory");
}

// ---------------------------------------------------------------------------
// Register-resident Gauss-Jordan 64x64 inversion (no pivoting; SPD / ~I).
// Thread (r = tid&63, cg = tid>>6) owns 32 cols of the 64x128 augmented matrix
// in registers. Pivot row/col double-buffered in shared -> 1 barrier/pivot.
// Pivot loop FULLY unrolled so all register-array indices are static.
// Deferred normalization (left half ends diagonal; divide at the end).
// ---------------------------------------------------------------------------
__device__ __noinline__ void gj_inv(const float* __restrict__ Ain, float* __restrict__ Aout) {
    __shared__ float pr[2][128];
    __shared__ float fc[2][64];
    int tid = threadIdx.x;
    int r = tid & 63, cg = tid >> 6, j0 = cg * 32;
    float a[32];
#pragma unroll
    for (int jj = 0; jj < 32; jj++) {
        int j = j0 + jj;
        a[jj] = (j < 64) ? Ain[r * 64 + j] : ((j - 64 == r) ? 1.f : 0.f);
    }
    if (cg == 0) fc[0][r] = a[0];
    if (r == 0) {
#pragma unroll
        for (int jj = 0; jj < 32; jj++) pr[0][j0 + jj] = a[jj];
    }
    __syncthreads();
    float mydiag = 1.f;
#pragma unroll
    for (int p = 0; p < 64; p++) {
        const int cur = p & 1, nxt = cur ^ 1;
        float apiv = fc[cur][p];
        float scale = fc[cur][r] / apiv;
        if (r == p) mydiag = apiv;
        if (r != p) {
#pragma unroll
            for (int jj = 0; jj < 32; jj++) a[jj] -= scale * pr[cur][j0 + jj];
        }
        if (p < 63) {
            const int q = p + 1;
            if (cg == (q >> 5)) fc[nxt][r] = a[q & 31];   // static index (unrolled)
            if (r == q) {
#pragma unroll
                for (int jj = 0; jj < 32; jj++) pr[nxt][j0 + jj] = a[jj];
            }
        }
        __syncthreads();
    }
    if (cg >= 2) {
        float dinv = 1.f / mydiag;
#pragma unroll
        for (int jj = 0; jj < 32; jj++)
            Aout[r * 64 + (j0 - 64) + jj] = a[jj] * dinv;
    }
}

// ---------------------------------------------------------------------------
// Small-GEMM helpers: one 16-row slab of a 64x64 output, 256 threads
// ---------------------------------------------------------------------------
__device__ void dot_nt256(const float* __restrict__ L, const float* __restrict__ R,
                          float* __restrict__ C, int slab) {
    int tid = threadIdx.x;
    int r = slab * 16 + (tid >> 4), c0 = (tid & 15) * 4;
    float s0 = 0.f, s1 = 0.f, s2 = 0.f, s3 = 0.f;
    for (int k4 = 0; k4 < 64; k4++) {
        float4 lv = *(const float4*)&L[r * 256 + k4 * 4];
        float4 a0 = *(const float4*)&R[(c0 + 0) * 256 + k4 * 4];
        float4 a1 = *(const float4*)&R[(c0 + 1) * 256 + k4 * 4];
        float4 a2 = *(const float4*)&R[(c0 + 2) * 256 + k4 * 4];
        float4 a3 = *(const float4*)&R[(c0 + 3) * 256 + k4 * 4];
        s0 += lv.x * a0.x + lv.y * a0.y + lv.z * a0.z + lv.w * a0.w;
        s1 += lv.x * a1.x + lv.y * a1.y + lv.z * a1.z + lv.w * a1.w;
        s2 += lv.x * a2.x + lv.y * a2.y + lv.z * a2.z + lv.w * a2.w;
        s3 += lv.x * a3.x + lv.y * a3.y + lv.z * a3.z + lv.w * a3.w;
    }
    *(float4*)&C[r * 64 + c0] = make_float4(s0, s1, s2, s3);
}

__device__ void dot64(const float* __restrict__ A, const float* __restrict__ B,
                      float* __restrict__ C, int slab, float* __restrict__ C2) {
    int tid = threadIdx.x;
    int r = slab * 16 + (tid >> 4), c0 = (tid & 15) * 4;
    float4 acc = make_float4(0.f, 0.f, 0.f, 0.f);
    for (int k = 0; k < 64; k++) {
        float av = A[r * 64 + k];
        float4 bv = *(const float4*)&B[k * 64 + c0];
        acc.x += av * bv.x; acc.y += av * bv.y;
        acc.z += av * bv.z; acc.w += av * bv.w;
    }
    *(float4*)&C[r * 64 + c0] = acc;
    if (C2) *(float4*)&C2[r * 64 + c0] = acc;
}

__device__ void dot64w(const float* __restrict__ A, const float* __restrict__ B,
                       const float* __restrict__ w, float scale,
                       float* __restrict__ C, int slab) {
    int tid = threadIdx.x;
    int r = slab * 16 + (tid >> 4), c0 = (tid & 15) * 4;
    float4 acc = make_float4(0.f, 0.f, 0.f, 0.f);
    for (int k = 0; k < 64; k++) {
        float av = A[r * 64 + k] * w[k];
        float4 bv = *(const float4*)&B[k * 64 + c0];
        acc.x += av * bv.x; acc.y += av * bv.y;
        acc.z += av * bv.z; acc.w += av * bv.w;
    }
    *(float4*)&C[r * 64 + c0] = make_float4(acc.x * scale, acc.y * scale,
                                            acc.z * scale, acc.w * scale);
}

// Fused: QtP = Qm^T diag(ex) Qm, QtQ = Qm^T Qm, U1 = AAt + LMB*Qm^T diag(ex^2) Qm
__device__ void qt_fused(const float* __restrict__ ex, int slab) {
    int tid = threadIdx.x;
    int r = slab * 16 + (tid >> 4), c0 = (tid & 15) * 4;
    float4 ap = make_float4(0, 0, 0, 0), aq = ap, au = ap;
    for (int k = 0; k < 64; k++) {
        float qr = g_Qm[k * 64 + r];
        float e = ex[k];
        float4 qc = *(const float4*)&g_Qm[k * 64 + c0];
        float t = qr * e, t2 = t * e;
        ap.x += t * qc.x;  ap.y += t * qc.y;  ap.z += t * qc.z;  ap.w += t * qc.w;
        aq.x += qr * qc.x; aq.y += qr * qc.y; aq.z += qr * qc.z; aq.w += qr * qc.w;
        au.x += t2 * qc.x; au.y += t2 * qc.y; au.z += t2 * qc.z; au.w += t2 * qc.w;
    }
    *(float4*)&g_QtP[r * 64 + c0] = ap;
    *(float4*)&g_QtQ[r * 64 + c0] = aq;
    float4 av = *(const float4*)&g_AAt[r * 64 + c0];
    *(float4*)&g_U1[r * 64 + c0] = make_float4(av.x + LMB * au.x, av.y + LMB * au.y,
                                               av.z + LMB * au.z, av.w + LMB * au.w);
}

// X <- X + X0 - M1 + LMB*diag(ey)*M2 + L3*M2 - L4*M4  (one slab)
__device__ void iterB_slab(int slab, const float* __restrict__ ey, float* __restrict__ out) {
    int tid = threadIdx.x;
    int r = slab * 16 + (tid >> 4), c0 = (tid & 15) * 4;
    float eyr = LMB * ey[r];
    float4 xv = *(const float4*)&g_X[r * 64 + c0];
    float4 x0 = *(const float4*)&g_X0[r * 64 + c0];
    float4 m1 = *(const float4*)&g_M1[r * 64 + c0];
    float4 m2 = *(const float4*)&g_M2[r * 64 + c0];
    float4 s = make_float4(xv.x + x0.x - m1.x + eyr * m2.x,
                           xv.y + x0.y - m1.y + eyr * m2.y,
                           xv.z + x0.z - m1.z + eyr * m2.z,
                           xv.w + x0.w - m1.w + eyr * m2.w);
    for (int k = 0; k < 64; k++) {
        float l3 = g_L3[r * 64 + k], l4 = g_L4[r * 64 + k];
        float4 a = *(const float4*)&g_M2[k * 64 + c0];
        float4 b = *(const float4*)&g_M4[k * 64 + c0];
        s.x += l3 * a.x - l4 * b.x;  s.y += l3 * a.y - l4 * b.y;
        s.z += l3 * a.z - l4 * b.z;  s.w += l3 * a.w - l4 * b.w;
    }
    *(float4*)&g_X[r * 64 + c0] = s;
    if (out) *(float4*)&out[r * 64 + c0] = s;
}

// ---------------------------------------------------------------------------
// Mega kernel: all post-reduce work, one 8-CTA cluster, phase-synchronized.
// ---------------------------------------------------------------------------
__global__ void __cluster_dims__(8, 1, 1) __launch_bounds__(256, 1)
mega(const float* __restrict__ sx, const float* __restrict__ ex,
     const float* __restrict__ ey, float* __restrict__ out) {
    int b = blockIdx.x;

    // P1: inversions of sx and S; AAt; first half of TA
    if (b == 0)      gj_inv(sx, g_Qm);
    else if (b == 1) gj_inv(g_S, g_Sinv);
    else if (b < 6)  dot_nt256(g_A, g_A, g_AAt, b - 2);
    else             dot_nt256(g_T, g_A, g_TA, b - 6);
    csync();

    // P2: inv(AAt); rest of TA; fused QtP/QtQ/U1; L3
    if (b == 0)      gj_inv(g_AAt, g_AAti);
    else if (b < 3)  dot_nt256(g_T, g_A, g_TA, b + 1);
    else if (b < 7)  qt_fused(ex, b - 3);
    else
        for (int s = 0; s < 4; s++) dot64w(g_Sinv, g_S, ey, LMB, g_L3, s);
    csync();

    // P3: R1, R2, R4, X0 (=TA*AAti, copied to X), L4   (17 units)
    for (int u = b; u < 17; u += 8) {
        if (u < 4)       dot64(g_U1, g_AAti, g_R1, u, 0);
        else if (u < 8)  dot64(g_QtP, g_AAti, g_R2, u - 4, 0);
        else if (u < 12) dot64(g_QtQ, g_AAti, g_R4, u - 8, 0);
        else if (u < 16) dot64(g_TA, g_AAti, g_X0, u - 12, g_X);
        else {
            int tid = threadIdx.x;
            for (int i = 0; i < 16; i++) {
                int o = tid * 16 + i;
                g_L4[o] = g_L3[o] * ey[o & 63];
            }
        }
    }
    csync();

    // Richardson iterations
    for (int it = 0; it < NITER; it++) {
        for (int u = b; u < 12; u += 8) {
            if (u < 4)      dot64(g_X, g_R1, g_M1, u, 0);
            else if (u < 8) dot64(g_X, g_R2, g_M2, u - 4, 0);
            else            dot64(g_X, g_R4, g_M4, u - 8, 0);
        }
        csync();
        if (b < 4) iterB_slab(b, ey, (it == NITER - 1) ? out : 0);
        csync();
    }
}

// ---------------------------------------------------------------------------
// Launch: graph-capturable, allocation-free, deterministic.  3 nodes.
// ---------------------------------------------------------------------------
extern "C" void kernel_launch(void* const* d_in, const int* in_sizes, int n_in,
                              void* d_out, int out_size) {
    const float *fx = 0, *fy = 0, *ex = 0, *ey = 0, *tx = 0, *ty = 0, *sx = 0, *sy = 0;
    int nFeat = 0, nEval = 0, nEvec = 0, nSq = 0;
    for (int i = 0; i < n_in; i++) {
        const float* p = (const float*)d_in[i];
        int n = in_sizes[i];
        if (n == VDIM * MDIM)    { if (nFeat++ == 0) fx = p; else fy = p; }
        else if (n == 64)        { if (nEval++ == 0) ex = p; else ey = p; }
        else if (n == 64 * VDIM) { if (nEvec++ == 0) tx = p; else ty = p; }
        else if (n == 64 * 64)   { if (nSq++   == 0) sx = p; else sy = p; }
    }

    dim3 gB(NCH, 4, 2);
    big_gemm<<<gB, 256>>>(fx, fy, tx, ty);
    reduce_AT<<<132, 256>>>(sy);
    mega<<<8, 256>>>(sx, ex, ey, (float*)d_out);
}

// round 8
// speedup vs baseline: 3.1227x; 1.1314x over previous
#include <cuda_runtime.h>

#define VDIM 5000
#define MDIM 256
#define NCH 63        // split-K chunks: 63*80 = 5040 >= 5000
#define CHUNK 80
#define LMB 0.001f
#define NITER 2

// ---------------------------------------------------------------------------
// Device scratch (allocation-free rule), 16B-aligned
// ---------------------------------------------------------------------------
__device__ __align__(16) float g_part[2 * NCH * 4 * 64 * 64];
__device__ __align__(16) float g_A[64 * 256], g_T[64 * 256];
__device__ __align__(16) float g_S[4096];
__device__ __align__(16) float g_AAt[4096], g_TA[4096];
__device__ __align__(16) float g_Qm[4096], g_Sinv[4096], g_AAti[4096];
__device__ __align__(16) float g_QtP[4096], g_QtQ[4096], g_U1[4096];
__device__ __align__(16) float g_L3[4096], g_L4[4096];
__device__ __align__(16) float g_R1[4096], g_R2[4096], g_R4[4096];
__device__ __align__(16) float g_X0[4096], g_X[4096];
__device__ __align__(16) float g_M1[4096], g_M2[4096], g_M4[4096];

// ---------------------------------------------------------------------------
// Big GEMMs: A = tx[64,V] @ fx[V,256], T = ty @ fy.  4x4 microtile, split-K.
// ---------------------------------------------------------------------------
__global__ void __launch_bounds__(256) big_gemm(
        const float* __restrict__ fx, const float* __restrict__ fy,
        const float* __restrict__ tx, const float* __restrict__ ty) {
    int ch = blockIdx.x, ct = blockIdx.y, mz = blockIdx.z;
    const float* f = mz ? fy : fx;
    const float* t = mz ? ty : tx;

    __shared__ __align__(16) float tsT[16][68];
    __shared__ __align__(16) float fs[16][64];

    int tid = threadIdx.x;
    int r0 = (tid >> 4) * 4;
    int c0 = (tid & 15) * 4;

    float acc[4][4];
#pragma unroll
    for (int i = 0; i < 4; i++)
#pragma unroll
        for (int j = 0; j < 4; j++) acc[i][j] = 0.f;

    int lr = tid >> 2, lkq = (tid & 3) * 4;
    int fkk = tid >> 4, fcb = (tid & 15) * 4;

    int k0 = ch * CHUNK;
    for (int sub = 0; sub < CHUNK / 16; ++sub) {
        int kb = k0 + sub * 16;
#pragma unroll
        for (int q = 0; q < 4; q++) {
            int k = kb + lkq + q;
            tsT[lkq + q][lr] = (k < VDIM) ? t[lr * VDIM + k] : 0.f;
        }
        {
            int k = kb + fkk;
            float4 fv = make_float4(0.f, 0.f, 0.f, 0.f);
            if (k < VDIM) fv = *(const float4*)&f[k * MDIM + ct * 64 + fcb];
            *(float4*)&fs[fkk][fcb] = fv;
        }
        __syncthreads();
#pragma unroll
        for (int kk = 0; kk < 16; kk++) {
            float4 av = *(const float4*)&tsT[kk][r0];
            float4 bv = *(const float4*)&fs[kk][c0];
            float a[4] = {av.x, av.y, av.z, av.w};
            float b[4] = {bv.x, bv.y, bv.z, bv.w};
#pragma unroll
            for (int i = 0; i < 4; i++)
#pragma unroll
                for (int j = 0; j < 4; j++) acc[i][j] += a[i] * b[j];
        }
        __syncthreads();
    }
    size_t base = (((size_t)mz * NCH + ch) * 4 + ct) * 4096;
#pragma unroll
    for (int i = 0; i < 4; i++)
        *(float4*)&g_part[base + (size_t)(r0 + i) * 64 + c0] =
            make_float4(acc[i][0], acc[i][1], acc[i][2], acc[i][3]);
}

// ---------------------------------------------------------------------------
// Cluster phase barrier
// ---------------------------------------------------------------------------
__device__ __forceinline__ void csync() {
    asm volatile("fence.acq_rel.cluster;" ::: "memory");
    asm volatile("barrier.cluster.arrive.aligned;" ::: "memory");
    asm volatile("barrier.cluster.wait.aligned;" ::: "memory");
}

// ---------------------------------------------------------------------------
// Register-resident Gauss-Jordan 64x64 inversion (no pivoting; SPD / ~I).
// ---------------------------------------------------------------------------
__device__ __noinline__ void gj_inv(const float* __restrict__ Ain, float* __restrict__ Aout) {
    __shared__ float pr[2][128];
    __shared__ float fc[2][64];
    int tid = threadIdx.x;
    int r = tid & 63, cg = tid >> 6, j0 = cg * 32;
    float a[32];
#pragma unroll
    for (int jj = 0; jj < 32; jj++) {
        int j = j0 + jj;
        a[jj] = (j < 64) ? Ain[r * 64 + j] : ((j - 64 == r) ? 1.f : 0.f);
    }
    if (cg == 0) fc[0][r] = a[0];
    if (r == 0) {
#pragma unroll
        for (int jj = 0; jj < 32; jj++) pr[0][j0 + jj] = a[jj];
    }
    __syncthreads();
    float mydiag = 1.f;
#pragma unroll
    for (int p = 0; p < 64; p++) {
        const int cur = p & 1, nxt = cur ^ 1;
        float apiv = fc[cur][p];
        float scale = __fdividef(fc[cur][r], apiv);
        if (r == p) mydiag = apiv;
        if (r != p) {
#pragma unroll
            for (int jj = 0; jj < 32; jj++) a[jj] -= scale * pr[cur][j0 + jj];
        }
        if (p < 63) {
            const int q = p + 1;
            if (cg == (q >> 5)) fc[nxt][r] = a[q & 31];
            if (r == q) {
#pragma unroll
                for (int jj = 0; jj < 32; jj++) pr[nxt][j0 + jj] = a[jj];
            }
        }
        __syncthreads();
    }
    if (cg >= 2) {
        float dinv = 1.f / mydiag;
#pragma unroll
        for (int jj = 0; jj < 32; jj++)
            Aout[r * 64 + (j0 - 64) + jj] = a[jj] * dinv;
    }
}

// ---------------------------------------------------------------------------
// Microtiled helpers: 2x4 register tile, 32-row half-matrix per call.
// thread: rp = tid>>4 (16 row-pairs), cq = tid&15 (16 col-quads)
// ---------------------------------------------------------------------------
// C[rb..rb+32) = A(64x64) * B(64x64) rows; optional duplicate C2
__device__ void dot64h(const float* __restrict__ A, const float* __restrict__ B,
                       float* __restrict__ C, int rb, float* __restrict__ C2) {
    int tid = threadIdx.x;
    int r = rb + (tid >> 4) * 2, c0 = (tid & 15) * 4;
    float4 a0 = make_float4(0.f, 0.f, 0.f, 0.f), a1 = a0;
#pragma unroll 8
    for (int k = 0; k < 64; k++) {
        float x0 = A[r * 64 + k], x1 = A[(r + 1) * 64 + k];
        float4 bv = *(const float4*)&B[k * 64 + c0];
        a0.x += x0 * bv.x; a0.y += x0 * bv.y; a0.z += x0 * bv.z; a0.w += x0 * bv.w;
        a1.x += x1 * bv.x; a1.y += x1 * bv.y; a1.z += x1 * bv.z; a1.w += x1 * bv.w;
    }
    *(float4*)&C[r * 64 + c0] = a0;
    *(float4*)&C[(r + 1) * 64 + c0] = a1;
    if (C2) {
        *(float4*)&C2[r * 64 + c0] = a0;
        *(float4*)&C2[(r + 1) * 64 + c0] = a1;
    }
}

// C[rb..rb+32) : C[r][c] = sum_k L[r*256+k]*R[c*256+k]  (K=256, NT form)
__device__ void dot_nt256h(const float* __restrict__ L, const float* __restrict__ R,
                           float* __restrict__ C, int rb) {
    int tid = threadIdx.x;
    int r = rb + (tid >> 4) * 2, c0 = (tid & 15) * 4;
    float s[2][4];
#pragma unroll
    for (int i = 0; i < 2; i++)
#pragma unroll
        for (int j = 0; j < 4; j++) s[i][j] = 0.f;
    for (int k4 = 0; k4 < 64; k4++) {
        float4 l0 = *(const float4*)&L[r * 256 + k4 * 4];
        float4 l1 = *(const float4*)&L[(r + 1) * 256 + k4 * 4];
#pragma unroll
        for (int j = 0; j < 4; j++) {
            float4 rv = *(const float4*)&R[(c0 + j) * 256 + k4 * 4];
            s[0][j] += l0.x * rv.x + l0.y * rv.y + l0.z * rv.z + l0.w * rv.w;
            s[1][j] += l1.x * rv.x + l1.y * rv.y + l1.z * rv.z + l1.w * rv.w;
        }
    }
    *(float4*)&C[r * 64 + c0] = make_float4(s[0][0], s[0][1], s[0][2], s[0][3]);
    *(float4*)&C[(r + 1) * 64 + c0] = make_float4(s[1][0], s[1][1], s[1][2], s[1][3]);
}

// rows rb..rb+32 of: QtP = Qm^T diag(ex) Qm, QtQ = Qm^T Qm,
//                    U1 = AAt + LMB*Qm^T diag(ex^2) Qm
__device__ void qt_fusedh(const float* __restrict__ ex, int rb) {
    int tid = threadIdx.x;
    int r = rb + (tid >> 4) * 2, c0 = (tid & 15) * 4;
    float4 p0 = make_float4(0.f, 0.f, 0.f, 0.f), p1 = p0;
    float4 q0 = p0, q1 = p0, u0 = p0, u1 = p0;
    for (int k = 0; k < 64; k++) {
        float a0 = g_Qm[k * 64 + r], a1 = g_Qm[k * 64 + r + 1];
        float e = ex[k];
        float4 qc = *(const float4*)&g_Qm[k * 64 + c0];
        float t0 = a0 * e, t1 = a1 * e, w0 = t0 * e, w1 = t1 * e;
        p0.x += t0 * qc.x; p0.y += t0 * qc.y; p0.z += t0 * qc.z; p0.w += t0 * qc.w;
        p1.x += t1 * qc.x; p1.y += t1 * qc.y; p1.z += t1 * qc.z; p1.w += t1 * qc.w;
        q0.x += a0 * qc.x; q0.y += a0 * qc.y; q0.z += a0 * qc.z; q0.w += a0 * qc.w;
        q1.x += a1 * qc.x; q1.y += a1 * qc.y; q1.z += a1 * qc.z; q1.w += a1 * qc.w;
        u0.x += w0 * qc.x; u0.y += w0 * qc.y; u0.z += w0 * qc.z; u0.w += w0 * qc.w;
        u1.x += w1 * qc.x; u1.y += w1 * qc.y; u1.z += w1 * qc.z; u1.w += w1 * qc.w;
    }
    *(float4*)&g_QtP[r * 64 + c0] = p0;
    *(float4*)&g_QtP[(r + 1) * 64 + c0] = p1;
    *(float4*)&g_QtQ[r * 64 + c0] = q0;
    *(float4*)&g_QtQ[(r + 1) * 64 + c0] = q1;
    float4 v0 = *(const float4*)&g_AAt[r * 64 + c0];
    float4 v1 = *(const float4*)&g_AAt[(r + 1) * 64 + c0];
    *(float4*)&g_U1[r * 64 + c0] =
        make_float4(v0.x + LMB * u0.x, v0.y + LMB * u0.y, v0.z + LMB * u0.z, v0.w + LMB * u0.w);
    *(float4*)&g_U1[(r + 1) * 64 + c0] =
        make_float4(v1.x + LMB * u1.x, v1.y + LMB * u1.y, v1.z + LMB * u1.z, v1.w + LMB * u1.w);
}

// Full L3 = LMB * Sinv*diag(ey)*S and L4 = L3*diag(ey), one CTA (2 halves)
__device__ void l3l4_unit(const float* __restrict__ ey) {
    int tid = threadIdx.x;
    int c0 = (tid & 15) * 4;
    float4 eyc = *(const float4*)&ey[c0];
    for (int h = 0; h < 2; h++) {
        int r = h * 32 + (tid >> 4) * 2;
        float4 a0 = make_float4(0.f, 0.f, 0.f, 0.f), a1 = a0;
        for (int k = 0; k < 64; k++) {
            float w = ey[k];
            float x0 = g_Sinv[r * 64 + k] * w, x1 = g_Sinv[(r + 1) * 64 + k] * w;
            float4 sv = *(const float4*)&g_S[k * 64 + c0];
            a0.x += x0 * sv.x; a0.y += x0 * sv.y; a0.z += x0 * sv.z; a0.w += x0 * sv.w;
            a1.x += x1 * sv.x; a1.y += x1 * sv.y; a1.z += x1 * sv.z; a1.w += x1 * sv.w;
        }
        float4 l30 = make_float4(LMB * a0.x, LMB * a0.y, LMB * a0.z, LMB * a0.w);
        float4 l31 = make_float4(LMB * a1.x, LMB * a1.y, LMB * a1.z, LMB * a1.w);
        *(float4*)&g_L3[r * 64 + c0] = l30;
        *(float4*)&g_L3[(r + 1) * 64 + c0] = l31;
        *(float4*)&g_L4[r * 64 + c0] =
            make_float4(l30.x * eyc.x, l30.y * eyc.y, l30.z * eyc.z, l30.w * eyc.w);
        *(float4*)&g_L4[(r + 1) * 64 + c0] =
            make_float4(l31.x * eyc.x, l31.y * eyc.y, l31.z * eyc.z, l31.w * eyc.w);
    }
}

// X <- X + X0 - M1 + LMB*diag(ey)*M2 + L3*M2 - L4*M4  (16-row slab)
__device__ void iterB_slab(int slab, const float* __restrict__ ey, float* __restrict__ out) {
    int tid = threadIdx.x;
    int r = slab * 16 + (tid >> 4), c0 = (tid & 15) * 4;
    float eyr = LMB * ey[r];
    float4 xv = *(const float4*)&g_X[r * 64 + c0];
    float4 x0 = *(const float4*)&g_X0[r * 64 + c0];
    float4 m1 = *(const float4*)&g_M1[r * 64 + c0];
    float4 m2 = *(const float4*)&g_M2[r * 64 + c0];
    float4 s = make_float4(xv.x + x0.x - m1.x + eyr * m2.x,
                           xv.y + x0.y - m1.y + eyr * m2.y,
                           xv.z + x0.z - m1.z + eyr * m2.z,
                           xv.w + x0.w - m1.w + eyr * m2.w);
    for (int k = 0; k < 64; k++) {
        float l3 = g_L3[r * 64 + k], l4 = g_L4[r * 64 + k];
        float4 a = *(const float4*)&g_M2[k * 64 + c0];
        float4 b = *(const float4*)&g_M4[k * 64 + c0];
        s.x += l3 * a.x - l4 * b.x;  s.y += l3 * a.y - l4 * b.y;
        s.z += l3 * a.z - l4 * b.z;  s.w += l3 * a.w - l4 * b.w;
    }
    *(float4*)&g_X[r * 64 + c0] = s;
    if (out) *(float4*)&out[r * 64 + c0] = s;
}

// ---------------------------------------------------------------------------
// Mega kernel: reduce + all small-matrix work, one 8-CTA cluster.
// ---------------------------------------------------------------------------
__global__ void __cluster_dims__(8, 1, 1) __launch_bounds__(256, 1)
mega(const float* __restrict__ sx, const float* __restrict__ sy,
     const float* __restrict__ ex, const float* __restrict__ ey,
     float* __restrict__ out) {
    int b = blockIdx.x;
    int tid = threadIdx.x;

    // P0: reduce split-K partials (CTA b handles mz=b>>2, ct=b&3); CTA0 also S
    {
        int mz = b >> 2, ct = b & 3;
        float* dst = mz ? g_T : g_A;
#pragma unroll
        for (int i = 0; i < 4; i++) {
            int oq = tid + i * 256;          // 0..1023: r = oq>>4, colquad = oq&15
            int r = oq >> 4, c = (oq & 15) * 4;
            float4 s = make_float4(0.f, 0.f, 0.f, 0.f);
            for (int ch = 0; ch < NCH; ch++) {
                float4 v = *(const float4*)&g_part[(((size_t)mz * NCH + ch) * 4 + ct) * 4096 + r * 64 + c];
                s.x += v.x; s.y += v.y; s.z += v.z; s.w += v.w;
            }
            *(float4*)&dst[r * 256 + ct * 64 + c] = s;
        }
        if (b == 0) {   // S = sy^T sy
            int c0 = (tid & 15) * 4;
            for (int h = 0; h < 2; h++) {
                int r = h * 32 + (tid >> 4) * 2;
                float4 a0 = make_float4(0.f, 0.f, 0.f, 0.f), a1 = a0;
                for (int k = 0; k < 64; k++) {
                    float s0 = sy[k * 64 + r], s1 = sy[k * 64 + r + 1];
                    float4 sc = *(const float4*)&sy[k * 64 + c0];
                    a0.x += s0 * sc.x; a0.y += s0 * sc.y; a0.z += s0 * sc.z; a0.w += s0 * sc.w;
                    a1.x += s1 * sc.x; a1.y += s1 * sc.y; a1.z += s1 * sc.z; a1.w += s1 * sc.w;
                }
                *(float4*)&g_S[r * 64 + c0] = a0;
                *(float4*)&g_S[(r + 1) * 64 + c0] = a1;
            }
        }
    }
    csync();

    // P1: gj(sx), gj(S), AAt (2 halves), TA (2 halves)
    if (b == 0)      gj_inv(sx, g_Qm);
    else if (b == 1) gj_inv(g_S, g_Sinv);
    else if (b < 4)  dot_nt256h(g_A, g_A, g_AAt, (b - 2) * 32);
    else if (b < 6)  dot_nt256h(g_T, g_A, g_TA, (b - 4) * 32);
    csync();

    // P2: gj(AAt) || qt_fused (QtP,QtQ,U1) || L3/L4
    if (b == 0)      gj_inv(g_AAt, g_AAti);
    else if (b < 3)  qt_fusedh(ex, (b - 1) * 32);
    else if (b == 3) l3l4_unit(ey);
    csync();

    // P3: R1, R2, R4, X0 (=TA*AAti, dup to X)
    if (b < 2)      dot64h(g_U1, g_AAti, g_R1, b * 32, 0);
    else if (b < 4) dot64h(g_QtP, g_AAti, g_R2, (b - 2) * 32, 0);
    else if (b < 6) dot64h(g_QtQ, g_AAti, g_R4, (b - 4) * 32, 0);
    else            dot64h(g_TA, g_AAti, g_X0, (b - 6) * 32, g_X);
    csync();

    // Richardson iterations
    for (int it = 0; it < NITER; it++) {
        if (b < 2)      dot64h(g_X, g_R1, g_M1, b * 32, 0);
        else if (b < 4) dot64h(g_X, g_R2, g_M2, (b - 2) * 32, 0);
        else if (b < 6) dot64h(g_X, g_R4, g_M4, (b - 4) * 32, 0);
        csync();
        if (b < 4) iterB_slab(b, ey, (it == NITER - 1) ? out : 0);
        csync();
    }
}

// ---------------------------------------------------------------------------
// Launch: graph-capturable, allocation-free, deterministic.  2 nodes.
// ---------------------------------------------------------------------------
extern "C" void kernel_launch(void* const* d_in, const int* in_sizes, int n_in,
                              void* d_out, int out_size) {
    const float *fx = 0, *fy = 0, *ex = 0, *ey = 0, *tx = 0, *ty = 0, *sx = 0, *sy = 0;
    int nFeat = 0, nEval = 0, nEvec = 0, nSq = 0;
    for (int i = 0; i < n_in; i++) {
        const float* p = (const float*)d_in[i];
        int n = in_sizes[i];
        if (n == VDIM * MDIM)    { if (nFeat++ == 0) fx = p; else fy = p; }
        else if (n == 64)        { if (nEval++ == 0) ex = p; else ey = p; }
        else if (n == 64 * VDIM) { if (nEvec++ == 0) tx = p; else ty = p; }
        else if (n == 64 * 64)   { if (nSq++   == 0) sx = p; else sy = p; }
    }

    dim3 gB(NCH, 4, 2);
    big_gemm<<<gB, 256>>>(fx, fy, tx, ty);
    mega<<<8, 256>>>(sx, sy, ex, ey, (float*)d_out);
}